// round 17
// baseline (speedup 1.0000x reference)
#include <cuda_runtime.h>
#include <cstdint>

#define RES   512
// exponent in cell units: (xk - i/512)^2*5000 == (xi - i)^2 * (5000/2^18)
#define C_CELL 0.019073486328125f   // 5000 / 262144, exact in fp32
#define HH     0.96257146f          // exp(-2*C_CELL)
// Dropped terms <= exp(-5000*(28/512)^2) = 3.2e-7 each (BAND=30 validated,
// ~100x margin remains vs the 1e-3 global-norm gate).
#define BAND  28.0f

#define RB   32               // region (block tile) size, both axes
#define NRB  16               // grid dim

#define FMA_F32X2(d, a, b) \
    asm("fma.rn.f32x2 %0, %1, %2, %0;" : "+l"(d) : "l"(a), "l"(b))
#define ADD_F32X2(d, a, b) \
    asm("add.rn.f32x2 %0, %1, %2;" : "=l"(d) : "l"(a), "l"(b))

// ---------------------------------------------------------------------------
// Single fused kernel: one block per 32x32 region (grid 16x16), 256 threads
// = 8 warps doing warp-autonomous split-K.
//  1. Prologue: thread evaluates 4 curves at t=(tid&127)/127 (uniform loads);
//     warp-private ballot compaction of in-region points (k-space split 8
//     ways across warps by construction).
//  2. Main loop (chunks of 4 points, no block barriers): 8 staging lanes per
//     point produce 32 ex + 32 ey via the Gaussian recurrence
//     f(m+1) = f(m) * r, r0 = exp((2d-1)C), r *= exp(-2C)
//     (2 __expf + 5 FMUL per 4 values; ey duplicated for f32x2); then each
//     lane accumulates a 4(i) x 8(j) microtile with 16 FFMA2.
//  3. Two-phase fixed-order 8-warp combine, coalesced STG.128.
// ---------------------------------------------------------------------------
__global__ __launch_bounds__(256) void k_fused(const float* __restrict__ curves,
                                               float* __restrict__ out) {
    __shared__ float2 wlist[8][128];              // 8 KB warp-private lists
    __shared__ float  sex [8][4][32];             // 4 KB
    __shared__ float  seyd[8][4][64];             // 8 KB (ey duplicated)
    __shared__ unsigned long long sacc[4][32][16];// 16 KB

    const int tid = threadIdx.x, lane = tid & 31, w = tid >> 5;
    const int i0 = blockIdx.x * RB, j0 = blockIdx.y * RB;

    // ---- 1. Bezier (4 curves at one t) + warp-private compaction ----------
    const float t = (float)(tid & 127) * (1.0f / 127.0f);
    const float ilo = (float)i0 - BAND, ihi = (float)(i0 + RB - 1) + BAND;
    const float jlo = (float)j0 - BAND, jhi = (float)(j0 + RB - 1) + BAND;
    const unsigned lmlt = (1u << lane) - 1u;
    int nkw = 0;
    #pragma unroll
    for (int u = 0; u < 4; u++) {
        const int c = (w >> 2) * 4 + u;          // warps 0-3: curves 0-3; 4-7: 4-7
        const float4* P4 = (const float4*)(curves + c * 8);
        float4 A = __ldg(P4);        // p0x p0y p1x p1y (uniform across block)
        float4 B = __ldg(P4 + 1);    // p2x p2y p3x p3y
        float a01 = A.x + (A.z - A.x) * t;
        float a12 = A.z + (B.x - A.z) * t;
        float a23 = B.x + (B.z - B.x) * t;
        float qa  = a01 + t * (a12 - a01);
        float qb  = a12 + t * (a23 - a12);
        float xi  = (qa + t * (qb - qa)) * (float)RES;
        a01 = A.y + (A.w - A.y) * t;
        a12 = A.w + (B.y - A.w) * t;
        a23 = B.y + (B.w - B.y) * t;
        qa  = a01 + t * (a12 - a01);
        qb  = a12 + t * (a23 - a12);
        float yi  = (qa + t * (qb - qa)) * (float)RES;

        bool ok = (xi >= ilo) & (xi <= ihi) & (yi >= jlo) & (yi <= jhi);
        unsigned m = __ballot_sync(0xffffffffu, ok);
        if (ok) wlist[w][nkw + __popc(m & lmlt)] = make_float2(xi, yi);
        nkw += __popc(m);
    }
    __syncwarp();

    // ---- 2. warp-autonomous main loop (chunks of 4 points) ----------------
    const int pl  = lane >> 3;      // point slot 0..3 (staging)
    const int sub = lane & 7;       // 4-cell group    (staging)
    const int tx  = lane & 7;       // i 4-group       (compute)
    const int ty  = lane >> 3;      // j 8-group       (compute)
    unsigned long long acc[16];
    #pragma unroll
    for (int s = 0; s < 16; s++) acc[s] = 0ull;

    for (int cb = 0; cb < nkw; cb += 4) {
        float ex4[4], ey8[8];
        int idx = cb + pl;
        if (idx < nkw) {
            float2 p = wlist[w][idx];
            // ex group via recurrence: f(m) = exp(-C (d - m)^2), cells base+m
            // f(m+1) = f(m) * r,  r0 = exp((2d - 1) C),  r *= exp(-2C)
            float d = p.x - (float)(i0 + sub * 4);
            float f = __expf(-d * d * C_CELL);
            float r = __expf((2.0f * d - 1.0f) * C_CELL);
            ex4[0] = f; f *= r;
            ex4[1] = f; r *= HH; f *= r;
            ex4[2] = f; r *= HH; f *= r;
            ex4[3] = f;
            // ey group (duplicated for f32x2)
            d = p.y - (float)(j0 + sub * 4);
            f = __expf(-d * d * C_CELL);
            r = __expf((2.0f * d - 1.0f) * C_CELL);
            ey8[0] = ey8[1] = f; f *= r;
            ey8[2] = ey8[3] = f; r *= HH; f *= r;
            ey8[4] = ey8[5] = f; r *= HH; f *= r;
            ey8[6] = ey8[7] = f;
        } else {
            #pragma unroll
            for (int q = 0; q < 4; q++) ex4[q] = 0.f;
            #pragma unroll
            for (int q = 0; q < 8; q++) ey8[q] = 0.f;
        }
        __syncwarp();                        // readers of prev chunk done
        *(float4*)&sex [w][pl][sub * 4] =
            make_float4(ex4[0], ex4[1], ex4[2], ex4[3]);
        *(float4*)&seyd[w][pl][sub * 8] =
            make_float4(ey8[0], ey8[1], ey8[2], ey8[3]);
        *(float4*)&seyd[w][pl][sub * 8 + 4] =
            make_float4(ey8[4], ey8[5], ey8[6], ey8[7]);
        __syncwarp();

        #pragma unroll
        for (int p = 0; p < 4; p++) {
            ulonglong2 ex2 = *(const ulonglong2*)&sex[w][p][tx * 4];
            #pragma unroll
            for (int q = 0; q < 4; q++) {
                ulonglong2 eyq =
                    *(const ulonglong2*)&seyd[w][p][ty * 16 + q * 4];
                FMA_F32X2(acc[q * 4 + 0], ex2.x, eyq.x);
                FMA_F32X2(acc[q * 4 + 1], ex2.y, eyq.x);
                FMA_F32X2(acc[q * 4 + 2], ex2.x, eyq.y);
                FMA_F32X2(acc[q * 4 + 3], ex2.y, eyq.y);
            }
        }
    }

    // ---- 3. two-phase fixed-order combine + write -------------------------
    if (w < 4) {
        #pragma unroll
        for (int s = 0; s < 16; s++) sacc[w][lane][s] = acc[s];
    }
    __syncthreads();
    if (w >= 4) {
        #pragma unroll
        for (int s = 0; s < 16; s++) {
            unsigned long long v;
            ADD_F32X2(v, sacc[w - 4][lane][s], acc[s]);
            sacc[w - 4][lane][s] = v;
        }
    }
    __syncthreads();
    {
        const int l = tid & 31, s2 = tid >> 5;   // lane slot, j sub-row
        ulonglong2 v = *(const ulonglong2*)&sacc[0][l][s2 * 2];
        #pragma unroll
        for (int g = 1; g < 4; g++) {
            ulonglong2 o = *(const ulonglong2*)&sacc[g][l][s2 * 2];
            unsigned long long tt;
            ADD_F32X2(tt, v.x, o.x); v.x = tt;
            ADD_F32X2(tt, v.y, o.y); v.y = tt;
        }
        int i = i0 + (l & 7) * 4;
        int j = j0 + (l >> 3) * 8 + s2;
        *(ulonglong2*)&out[j * RES + i] = v;
    }
}

// ---------------------------------------------------------------------------
extern "C" void kernel_launch(void* const* d_in, const int* in_sizes, int n_in,
                              void* d_out, int out_size) {
    const float* curves = (const float*)d_in[0];
    float* out = (float*)d_out;
    dim3 grid(NRB, NRB);
    k_fused<<<grid, 256>>>(curves, out);
}